// round 1
// baseline (speedup 1.0000x reference)
#include <cuda_runtime.h>
#include <cuda_bf16.h>

#define R_    512
#define C_    256
#define H_    200
#define W_    200
#define OUTK  7
#define HW_   (H_*W_)

// Per-roi tap tables: [r][axis(0=y,1=x)][bin(7)][tap(4)]
__device__ int   g_idx[R_*2*OUTK*4];
__device__ float g_w  [R_*2*OUTK*4];
__device__ int   g_boff[R_];            // batch element offset b*C*H*W

// ---------------------------------------------------------------------------
// Precompute: one thread per roi. For each axis and output bin, emit the 4
// (index, weight) taps (2 samples x 2 bilinear taps), matching the reference's
// _axis_weights semantics exactly (valid window [-1, limit], clamp, floor).
// ---------------------------------------------------------------------------
__global__ void precompute_taps(const float* __restrict__ rois) {
    int r = blockIdx.x * blockDim.x + threadIdx.x;
    if (r >= R_) return;
    const float* ro = rois + r * 5;
    int b = (int)ro[0];
    g_boff[r] = b * (C_ * HW_);

    // axis 0 = y (roi cols y1=2, y2=4), axis 1 = x (cols x1=1, x2=3)
    float p1[2] = { ro[2] * 0.25f, ro[1] * 0.25f };
    float p2[2] = { ro[4] * 0.25f, ro[3] * 0.25f };

    #pragma unroll
    for (int ax = 0; ax < 2; ax++) {
        float start = p1[ax];
        float sz    = fmaxf(p2[ax] - p1[ax], 1.0f);
        float bin   = sz / (float)OUTK;
        float limit = 200.0f;  // H == W == 200
        #pragma unroll
        for (int o = 0; o < OUTK; o++) {
            #pragma unroll
            for (int s = 0; s < 2; s++) {
                // sample position: start + (o*2 + s + 0.5)/2 * bin
                float y = start + ((float)o + ((float)s + 0.5f) * 0.5f) * bin;
                bool valid = (y >= -1.0f) && (y <= limit);
                float yc = fminf(fmaxf(y, 0.0f), limit - 1.0f);
                int   yl = (int)floorf(yc);
                int   yh = min(yl + 1, (int)limit - 1);
                float l  = yc - (float)yl;
                float w0 = valid ? (1.0f - l) : 0.0f;
                float w1 = valid ? l          : 0.0f;
                int base = ((r * 2 + ax) * OUTK + o) * 4 + s * 2;
                g_idx[base]     = yl;  g_idx[base + 1] = yh;
                g_w  [base]     = w0;  g_w  [base + 1] = w1;
            }
        }
    }
}

// ---------------------------------------------------------------------------
// Main gather kernel.
// Grid: (7, 512) = (out_y, roi). Block: 256 threads = 8 warps.
// Warp lane -> (out_x, x-tap): lane = ox*4 + jx, lanes 28..31 duplicate the
// last tap (same addresses, no extra sectors) and never store.
// Each warp strides over channels (c = warp, warp+8, ...), doing 4 coalesced
// feature row loads per channel (x-taps of all 7 bins are monotone in x, so
// one warp-LDG touches only ~2-3 sectors of one feature row).
// Shfl-reduce groups of 4 lanes, lanes {0,4,...,24} store the 7 contiguous
// outputs out[r][c][oy][0..6].
// ---------------------------------------------------------------------------
__global__ __launch_bounds__(256) void roialign_kernel(
    const float* __restrict__ feat, float* __restrict__ out)
{
    int oy = blockIdx.x;
    int r  = blockIdx.y;

    __shared__ int   s_xi[28];
    __shared__ float s_xw[28];
    __shared__ int   s_yi[4];
    __shared__ float s_yw[4];
    __shared__ int   s_boff;

    int tid = threadIdx.x;
    if (tid < 28) {
        int base = ((r * 2 + 1) * OUTK + (tid >> 2)) * 4 + (tid & 3);
        s_xi[tid] = g_idx[base];
        s_xw[tid] = g_w[base];
    } else if (tid < 32) {
        int t = tid - 28;
        int base = ((r * 2 + 0) * OUTK + oy) * 4 + t;
        s_yi[t] = g_idx[base];
        s_yw[t] = g_w[base];
    } else if (tid == 32) {
        s_boff = g_boff[r];
    }
    __syncthreads();

    int lane = tid & 31;
    int warp = tid >> 5;
    int l    = min(lane, 27);

    int   xi = s_xi[l];
    float xw = s_xw[l];
    float yw0 = s_yw[0], yw1 = s_yw[1], yw2 = s_yw[2], yw3 = s_yw[3];
    int off0 = s_yi[0] * W_ + xi;
    int off1 = s_yi[1] * W_ + xi;
    int off2 = s_yi[2] * W_ + xi;
    int off3 = s_yi[3] * W_ + xi;

    const float* fb = feat + s_boff;
    int  ox      = l >> 2;
    bool doStore = (lane < 28) && ((lane & 3) == 0);
    float* orow  = out + ((size_t)(r * C_) * OUTK + oy) * OUTK + ox;

    #pragma unroll 4
    for (int c = warp; c < C_; c += 8) {
        const float* f = fb + c * HW_;
        float acc = yw0 * __ldg(f + off0)
                  + yw1 * __ldg(f + off1)
                  + yw2 * __ldg(f + off2)
                  + yw3 * __ldg(f + off3);
        acc *= xw;
        acc += __shfl_xor_sync(0xffffffffu, acc, 1);
        acc += __shfl_xor_sync(0xffffffffu, acc, 2);
        if (doStore) orow[(size_t)c * (OUTK * OUTK)] = acc * 0.25f;
    }
}

extern "C" void kernel_launch(void* const* d_in, const int* in_sizes, int n_in,
                              void* d_out, int out_size) {
    // features: 4*256*200*200 = 40,960,000 elems; rois: 512*5 = 2560 elems.
    const float* feat = (const float*)d_in[0];
    const float* rois = (const float*)d_in[1];
    if (n_in >= 2 && in_sizes[0] == R_ * 5) {  // defensive against input order
        feat = (const float*)d_in[1];
        rois = (const float*)d_in[0];
    }
    float* out = (float*)d_out;

    precompute_taps<<<2, 256>>>(rois);
    dim3 grid(OUTK, R_);
    roialign_kernel<<<grid, 256>>>(feat, out);
}

// round 2
// speedup vs baseline: 1.3989x; 1.3989x over previous
#include <cuda_runtime.h>
#include <cuda_bf16.h>

#define R_    512
#define C_    256
#define H_    200
#define W_    200
#define OUTK  7
#define HW_   (H_*W_)

// ---------------------------------------------------------------------------
// Single fused kernel.
// Grid: (7, 512) = (out_y, roi). Block: 256 threads = 8 warps.
//
// Phase 1 (threads 0..32): compute bilinear tap tables for this (roi, oy)
// directly from rois — 28 x-taps (7 bins x 2 samples x 2 taps) and 4 y-taps —
// matching the reference _axis_weights semantics (valid window [-1, 200],
// clamp to [0,199], floor, lerp).
//
// Phase 2: warp lane -> (out_x, x-tap): lane = ox*4 + jx. Lanes 28..31
// duplicate lane 27's addresses (no extra sectors, never store). Each warp
// strides channels two-at-a-time (c, c+8; stride 16) giving 8 independent
// LDGs per iteration to cover L2/DRAM latency. 4-lane shfl-reduce, lanes
// {0,4,...,24} store the 7 outputs out[r][c][oy][0..6].
// ---------------------------------------------------------------------------
__global__ __launch_bounds__(256) void roialign_kernel(
    const float* __restrict__ feat, const float* __restrict__ rois,
    float* __restrict__ out)
{
    int oy = blockIdx.x;
    int r  = blockIdx.y;

    __shared__ int   s_xi[28];
    __shared__ float s_xw[28];
    __shared__ int   s_yi[4];
    __shared__ float s_yw[4];
    __shared__ int   s_boff;

    int tid = threadIdx.x;
    if (tid < 32) {
        const float* ro = rois + r * 5;
        // axis select: x for tid<28, y for tid>=28
        bool isx = tid < 28;
        float p1 = (isx ? ro[1] : ro[2]) * 0.25f;
        float p2 = (isx ? ro[3] : ro[4]) * 0.25f;
        float bin = fmaxf(p2 - p1, 1.0f) * (1.0f / (float)OUTK);

        int o, s, tap;
        if (isx) { o = tid >> 2; s = (tid >> 1) & 1; tap = tid & 1; }
        else     { int t = tid - 28; o = oy; s = t >> 1; tap = t & 1; }

        float y = p1 + ((float)o + ((float)s + 0.5f) * 0.5f) * bin;
        bool valid = (y >= -1.0f) && (y <= 200.0f);
        float yc = fminf(fmaxf(y, 0.0f), 199.0f);
        int   yl = (int)floorf(yc);
        int   yh = min(yl + 1, 199);
        float l  = yc - (float)yl;
        float wv = tap ? l : (1.0f - l);
        if (!valid) wv = 0.0f;
        int   iv = tap ? yh : yl;

        if (isx) { s_xi[tid] = iv; s_xw[tid] = wv; }
        else     { s_yi[tid - 28] = iv; s_yw[tid - 28] = wv; }
        if (tid == 0) s_boff = (int)ro[0] * (C_ * HW_);
    }
    __syncthreads();

    int lane = tid & 31;
    int warp = tid >> 5;
    int l    = min(lane, 27);

    int   xi = s_xi[l];
    float xw = s_xw[l];
    float yw0 = s_yw[0], yw1 = s_yw[1], yw2 = s_yw[2], yw3 = s_yw[3];
    int off0 = s_yi[0] * W_ + xi;
    int off1 = s_yi[1] * W_ + xi;
    int off2 = s_yi[2] * W_ + xi;
    int off3 = s_yi[3] * W_ + xi;

    const float* fb = feat + s_boff;
    int  ox      = l >> 2;
    bool doStore = (lane < 28) && ((lane & 3) == 0);
    float* orow  = out + ((size_t)(r * C_) * OUTK + oy) * OUTK + ox;

    // Two channels per iteration: 8 independent LDGs in flight per iter,
    // paired shfl-reduces pipeline the shuffle latency.
    #pragma unroll 2
    for (int c = warp; c < C_; c += 16) {
        const float* f1 = fb + c * HW_;
        const float* f2 = fb + (c + 8) * HW_;
        float v10 = __ldg(f1 + off0), v11 = __ldg(f1 + off1);
        float v12 = __ldg(f1 + off2), v13 = __ldg(f1 + off3);
        float v20 = __ldg(f2 + off0), v21 = __ldg(f2 + off1);
        float v22 = __ldg(f2 + off2), v23 = __ldg(f2 + off3);

        float a1 = yw0 * v10 + yw1 * v11 + yw2 * v12 + yw3 * v13;
        float a2 = yw0 * v20 + yw1 * v21 + yw2 * v22 + yw3 * v23;
        a1 *= xw;
        a2 *= xw;
        a1 += __shfl_xor_sync(0xffffffffu, a1, 1);
        a2 += __shfl_xor_sync(0xffffffffu, a2, 1);
        a1 += __shfl_xor_sync(0xffffffffu, a1, 2);
        a2 += __shfl_xor_sync(0xffffffffu, a2, 2);
        if (doStore) {
            orow[(size_t)c * (OUTK * OUTK)]       = a1 * 0.25f;
            orow[(size_t)(c + 8) * (OUTK * OUTK)] = a2 * 0.25f;
        }
    }
}

extern "C" void kernel_launch(void* const* d_in, const int* in_sizes, int n_in,
                              void* d_out, int out_size) {
    const float* feat = (const float*)d_in[0];
    const float* rois = (const float*)d_in[1];
    if (n_in >= 2 && in_sizes[0] == R_ * 5) {  // defensive against input order
        feat = (const float*)d_in[1];
        rois = (const float*)d_in[0];
    }
    float* out = (float*)d_out;

    dim3 grid(OUTK, R_);
    roialign_kernel<<<grid, 256>>>(feat, rois, out);
}

// round 3
// speedup vs baseline: 1.5072x; 1.0774x over previous
#include <cuda_runtime.h>
#include <cuda_bf16.h>

#define R_    512
#define C_    256
#define H_    200
#define W_    200
#define OUTK  7
#define HW_   (H_*W_)
#define CHUNK 32   // channels per block (grid.z = C_/CHUNK phases, z slowest)

// ---------------------------------------------------------------------------
// Grid: (7, 512, 8) = (out_y, roi, channel-chunk). Block: 256 threads.
// z is slowest in CTA launch order, so all (oy, roi) blocks of one channel
// chunk execute as ~3 consecutive waves: the per-phase feature working set
// (all-roi patch coverage x 32 channels ~ 17 MB) fits in L2, converting
// cross-roi spatial overlap into L2 hits instead of DRAM refetches.
//
// Phase 1 (threads 0..31): recompute bilinear tap tables for this (roi, oy)
// from rois (reference _axis_weights semantics: valid window [-1,200],
// clamp [0,199], floor, lerp).
//
// Phase 2: lane -> (out_x, x-tap): lane = ox*4 + jx (lanes 28..31 duplicate
// lane 27, never store). Each warp covers 4 channels of the chunk
// (w, w+8, w+16, w+24) as two fully-unrolled 2-channel iterations ->
// 16 independent LDGs in flight. 4-lane shfl reduce; lanes {0,4,..,24}
// store the 7 contiguous outputs out[r][c][oy][0..6].
// ---------------------------------------------------------------------------
__global__ __launch_bounds__(256) void roialign_kernel(
    const float* __restrict__ feat, const float* __restrict__ rois,
    float* __restrict__ out)
{
    int oy  = blockIdx.x;
    int r   = blockIdx.y;
    int ch0 = blockIdx.z * CHUNK;

    __shared__ int   s_xi[28];
    __shared__ float s_xw[28];
    __shared__ int   s_yi[4];
    __shared__ float s_yw[4];
    __shared__ int   s_boff;

    int tid = threadIdx.x;
    if (tid < 32) {
        const float* ro = rois + r * 5;
        bool isx = tid < 28;
        float p1 = (isx ? ro[1] : ro[2]) * 0.25f;
        float p2 = (isx ? ro[3] : ro[4]) * 0.25f;
        float bin = fmaxf(p2 - p1, 1.0f) * (1.0f / (float)OUTK);

        int o, s, tap;
        if (isx) { o = tid >> 2; s = (tid >> 1) & 1; tap = tid & 1; }
        else     { int t = tid - 28; o = oy; s = t >> 1; tap = t & 1; }

        float y = p1 + ((float)o + ((float)s + 0.5f) * 0.5f) * bin;
        bool valid = (y >= -1.0f) && (y <= 200.0f);
        float yc = fminf(fmaxf(y, 0.0f), 199.0f);
        int   yl = (int)floorf(yc);
        int   yh = min(yl + 1, 199);
        float l  = yc - (float)yl;
        float wv = tap ? l : (1.0f - l);
        if (!valid) wv = 0.0f;
        int   iv = tap ? yh : yl;

        if (isx) { s_xi[tid] = iv; s_xw[tid] = wv; }
        else     { s_yi[tid - 28] = iv; s_yw[tid - 28] = wv; }
        if (tid == 0) s_boff = (int)ro[0] * (C_ * HW_);
    }
    __syncthreads();

    int lane = tid & 31;
    int warp = tid >> 5;
    int l    = min(lane, 27);

    int   xi = s_xi[l];
    float xw = s_xw[l];
    float yw0 = s_yw[0], yw1 = s_yw[1], yw2 = s_yw[2], yw3 = s_yw[3];
    int off0 = s_yi[0] * W_ + xi;
    int off1 = s_yi[1] * W_ + xi;
    int off2 = s_yi[2] * W_ + xi;
    int off3 = s_yi[3] * W_ + xi;

    const float* fb = feat + s_boff + (size_t)ch0 * HW_;
    int  ox      = l >> 2;
    bool doStore = (lane < 28) && ((lane & 3) == 0);
    float* orow  = out + (((size_t)r * C_ + ch0) * OUTK + oy) * OUTK + ox;

    // 4 channels per warp: two fully-unrolled 2-channel iterations
    // -> 16 independent LDGs visible to the scheduler.
    #pragma unroll
    for (int i = 0; i < 2; i++) {
        int c = warp + i * 16;
        const float* f1 = fb + c * HW_;
        const float* f2 = fb + (c + 8) * HW_;
        float v10 = __ldg(f1 + off0), v11 = __ldg(f1 + off1);
        float v12 = __ldg(f1 + off2), v13 = __ldg(f1 + off3);
        float v20 = __ldg(f2 + off0), v21 = __ldg(f2 + off1);
        float v22 = __ldg(f2 + off2), v23 = __ldg(f2 + off3);

        float a1 = yw0 * v10 + yw1 * v11 + yw2 * v12 + yw3 * v13;
        float a2 = yw0 * v20 + yw1 * v21 + yw2 * v22 + yw3 * v23;
        a1 *= xw;
        a2 *= xw;
        a1 += __shfl_xor_sync(0xffffffffu, a1, 1);
        a2 += __shfl_xor_sync(0xffffffffu, a2, 1);
        a1 += __shfl_xor_sync(0xffffffffu, a1, 2);
        a2 += __shfl_xor_sync(0xffffffffu, a2, 2);
        if (doStore) {
            orow[(size_t)c * (OUTK * OUTK)]       = a1 * 0.25f;
            orow[(size_t)(c + 8) * (OUTK * OUTK)] = a2 * 0.25f;
        }
    }
}

extern "C" void kernel_launch(void* const* d_in, const int* in_sizes, int n_in,
                              void* d_out, int out_size) {
    const float* feat = (const float*)d_in[0];
    const float* rois = (const float*)d_in[1];
    if (n_in >= 2 && in_sizes[0] == R_ * 5) {  // defensive against input order
        feat = (const float*)d_in[1];
        rois = (const float*)d_in[0];
    }
    float* out = (float*)d_out;

    dim3 grid(OUTK, R_, C_ / CHUNK);
    roialign_kernel<<<grid, 256>>>(feat, rois, out);
}